// round 16
// baseline (speedup 1.0000x reference)
#include <cuda_runtime.h>
#include <cuda_bf16.h>

#define BLK        128
#define NWARP      4
#define GRID       152                    // 1 block/SM, persistent
#define WROWS      24                     // rows per group (contiguous WROWS*T floats)
#define NSLOT      3                      // lookahead-2 pipeline
#define SLOT_BYTES 9600                   // per array: 24 rows x up to 100 f32
#define SLOT_FLOATS (SLOT_BYTES / 4)
#define SMEM_BYTES (NWARP * NSLOT * 2 * SLOT_BYTES)   // 230400 B -> 1 block/SM

// Scratch (alloc-free rule). g_tick wraps to 0 every launch -> graph-replay safe.
__device__ float g_partials[GRID];
__device__ unsigned int g_tick;

__device__ __forceinline__ void mbar_init(unsigned addr, unsigned count) {
    asm volatile("mbarrier.init.shared.b64 [%0], %1;" :: "r"(addr), "r"(count) : "memory");
}
__device__ __forceinline__ void mbar_expect_tx(unsigned addr, unsigned bytes) {
    asm volatile("mbarrier.arrive.expect_tx.shared.b64 _, [%0], %1;"
                 :: "r"(addr), "r"(bytes) : "memory");
}
__device__ __forceinline__ void bulk_g2s(unsigned dst, const void* src,
                                         unsigned bytes, unsigned mbar) {
    asm volatile("cp.async.bulk.shared::cta.global.mbarrier::complete_tx::bytes "
                 "[%0], [%1], %2, [%3];"
                 :: "r"(dst), "l"(src), "r"(bytes), "r"(mbar) : "memory");
}
__device__ __forceinline__ void mbar_wait(unsigned addr, unsigned parity) {
    asm volatile(
        "{\n\t"
        ".reg .pred P;\n\t"
        "WAIT_%=:\n\t"
        "mbarrier.try_wait.parity.acquire.cta.shared::cta.b64 P, [%0], %1, 0x989680;\n\t"
        "@P bra.uni DONE_%=;\n\t"
        "bra.uni WAIT_%=;\n\t"
        "DONE_%=:\n\t"
        "}"
        :: "r"(addr), "r"(parity) : "memory");
}

__global__ void __launch_bounds__(BLK) spike_loss_kernel(
    const float* __restrict__ outputs,
    const float* __restrict__ target,
    const int* __restrict__ n_steps_p,
    const int* __restrict__ tau_p,
    long long total_elems,
    float* __restrict__ out)
{
    extern __shared__ float smem[];
    __shared__ alignas(8) unsigned long long mbar_store[NWARP][NSLOT];

    const int   T       = *n_steps_p;
    const float inv_tau = 1.0f / (float)(*tau_p);
    const float decay   = 1.0f - inv_tau;
    const long long rows = (T > 0) ? total_elems / (long long)T : 0;

    const int tid  = threadIdx.x;
    const int wid  = tid >> 5;
    const int lane = tid & 31;
    float acc = 0.0f;

    const bool fast = (T >= 4) && ((T & 3) == 0) && (WROWS * T * 4 <= SLOT_BYTES);

    long long fast_rows = 0;

    if (fast) {
        // ===== fast path: 4 warps/SM, 3-slot bulk-copy pipeline (lookahead 2) =====
        const unsigned sm_base   = (unsigned)__cvta_generic_to_shared(smem);
        const unsigned mbar_base = (unsigned)__cvta_generic_to_shared(&mbar_store[0][0]);

        if (tid == 0) {
            #pragma unroll
            for (int i = 0; i < NWARP * NSLOT; ++i)
                mbar_init(mbar_base + 8u * i, 1);
        }
        __syncthreads();

        const long long ngroups  = rows / WROWS;
        fast_rows = ngroups * WROWS;
        const int  nstreams = GRID * NWARP;            // 608 independent streams
        const int  sid      = blockIdx.x * NWARP + wid;
        long long n_ci = 0;
        if ((long long)sid < ngroups)
            n_ci = (ngroups - sid + nstreams - 1) / nstreams;

        const unsigned bytes_arr = (unsigned)(WROWS * T * 4);
        const int T4 = T >> 2;

        auto slot_f = [&](int s, int a) -> unsigned {
            return (unsigned)(((wid * NSLOT + s) * 2 + a) * SLOT_FLOATS);
        };
        auto mb_addr = [&](int s) -> unsigned {
            return mbar_base + 8u * (unsigned)(wid * NSLOT + s);
        };

        auto issue = [&](long long ci) {
            const int s = (int)(ci % NSLOT);
            const long long g = (long long)sid + ci * nstreams;
            const long long e0 = g * (long long)WROWS * T;
            if (lane == 0) {
                const unsigned mb = mb_addr(s);
                mbar_expect_tx(mb, 2 * bytes_arr);
                bulk_g2s(sm_base + slot_f(s, 0) * 4, target  + e0, bytes_arr, mb);
                bulk_g2s(sm_base + slot_f(s, 1) * 4, outputs + e0, bytes_arr, mb);
            }
        };

        // prologue: 2 chunk-pairs in flight; loop keeps lookahead at 2
        if (n_ci > 0) issue(0);
        if (n_ci > 1) issue(1);

        for (long long ci = 0; ci < n_ci; ++ci) {
            const int s = (int)(ci % NSLOT);
            mbar_wait(mb_addr(s), (unsigned)((ci / NSLOT) & 1));

            // slot of ci-1 was freed last iteration -> issue ci+2 before compute
            if (ci + 2 < n_ci) issue(ci + 2);

            if (lane < WROWS) {
                // lane = row within group; stride T floats (conflict-free for T%8==4)
                const float4* xt = (const float4*)(smem + slot_f(s, 0) + lane * T);
                const float4* xo = (const float4*)(smem + slot_f(s, 1) + lane * T);
                float syn = 0.0f;
                #pragma unroll 5
                for (int j = 0; j < T4; ++j) {
                    const float4 x = xt[j];
                    const float4 o = xo[j];
                    float e;
                    syn = fmaf(syn, decay, x.x); e = fmaf(-syn, inv_tau, o.x); acc = fmaf(e, e, acc);
                    syn = fmaf(syn, decay, x.y); e = fmaf(-syn, inv_tau, o.y); acc = fmaf(e, e, acc);
                    syn = fmaf(syn, decay, x.z); e = fmaf(-syn, inv_tau, o.z); acc = fmaf(e, e, acc);
                    syn = fmaf(syn, decay, x.w); e = fmaf(-syn, inv_tau, o.w); acc = fmaf(e, e, acc);
                }
            }
            __syncwarp();                       // all lanes done reading slot s
        }
    }

    // ===== tail / generic path: scalar thread-per-row from global =====
    if (T > 0) {
        for (long long row = fast_rows + (long long)blockIdx.x * BLK + tid;
             row < rows; row += (long long)GRID * BLK) {
            const float* tg = target  + row * (long long)T;
            const float* op = outputs + row * (long long)T;
            float syn = 0.0f;
            for (int t = 0; t < T; ++t) {
                syn = fmaf(syn, decay, tg[t]);
                const float e = fmaf(-syn, inv_tau, op[t]);
                acc = fmaf(e, e, acc);
            }
        }
    }

    // ---- block reduce ----
    #pragma unroll
    for (int off = 16; off > 0; off >>= 1)
        acc += __shfl_xor_sync(0xFFFFFFFF, acc, off);

    __shared__ float wsum[NWARP];
    if (lane == 0) wsum[wid] = acc;
    __syncthreads();

    __shared__ bool is_last;
    if (tid == 0) {
        float s = 0.0f;
        #pragma unroll
        for (int i = 0; i < NWARP; ++i) s += wsum[i];
        g_partials[blockIdx.x] = s;
        __threadfence();
        const unsigned prev = atomicInc(&g_tick, GRID - 1);   // wraps to 0 each launch
        is_last = (prev == GRID - 1);
    }
    __syncthreads();

    if (is_last) {
        double d = 0.0;
        for (int i = tid; i < GRID; i += BLK)
            d += (double)g_partials[i];
        #pragma unroll
        for (int off = 16; off > 0; off >>= 1)
            d += __shfl_xor_sync(0xFFFFFFFF, d, off);
        __shared__ double dsum[NWARP];
        if (lane == 0) dsum[wid] = d;
        __syncthreads();
        if (tid == 0) {
            double t = 0.0;
            #pragma unroll
            for (int i = 0; i < NWARP; ++i) t += dsum[i];
            out[0] = (float)(0.5 * t);
        }
    }
}

extern "C" void kernel_launch(void* const* d_in, const int* in_sizes, int n_in,
                              void* d_out, int out_size)
{
    const float* outputs = (const float*)d_in[0];
    const float* target  = (const float*)d_in[1];
    const int*   n_steps = (const int*)d_in[2];
    const int*   tau_s   = (const int*)d_in[3];
    float*       out     = (float*)d_out;

    const long long total = (long long)in_sizes[0];

    cudaFuncSetAttribute(spike_loss_kernel,
                         cudaFuncAttributeMaxDynamicSharedMemorySize, SMEM_BYTES);
    spike_loss_kernel<<<GRID, BLK, SMEM_BYTES>>>(outputs, target, n_steps, tau_s, total, out);
}

// round 17
// speedup vs baseline: 1.0272x; 1.0272x over previous
#include <cuda_runtime.h>
#include <cuda_bf16.h>

#define BLK        128
#define NWARP      4
#define GRID       152                    // 1 block/SM, persistent
#define WROWS      32                     // rows per group (contiguous WROWS*T floats)
#define NSLOT      2
#define SLOT_BYTES 12800                  // per array: 32 rows x up to 100 f32
#define SLOT_FLOATS (SLOT_BYTES / 4)
#define SMEM_BYTES (NWARP * NSLOT * 2 * SLOT_BYTES)   // 204800 B -> 1 block/SM

// Scratch (alloc-free rule). g_tick wraps to 0 every launch -> graph-replay safe.
__device__ float g_partials[GRID];
__device__ unsigned int g_tick;

__device__ __forceinline__ void mbar_init(unsigned addr, unsigned count) {
    asm volatile("mbarrier.init.shared.b64 [%0], %1;" :: "r"(addr), "r"(count) : "memory");
}
__device__ __forceinline__ void mbar_expect_tx(unsigned addr, unsigned bytes) {
    asm volatile("mbarrier.arrive.expect_tx.shared.b64 _, [%0], %1;"
                 :: "r"(addr), "r"(bytes) : "memory");
}
__device__ __forceinline__ void bulk_g2s(unsigned dst, const void* src,
                                         unsigned bytes, unsigned mbar) {
    asm volatile("cp.async.bulk.shared::cta.global.mbarrier::complete_tx::bytes "
                 "[%0], [%1], %2, [%3];"
                 :: "r"(dst), "l"(src), "r"(bytes), "r"(mbar) : "memory");
}
__device__ __forceinline__ void mbar_wait(unsigned addr, unsigned parity) {
    asm volatile(
        "{\n\t"
        ".reg .pred P;\n\t"
        "WAIT_%=:\n\t"
        "mbarrier.try_wait.parity.acquire.cta.shared::cta.b64 P, [%0], %1, 0x989680;\n\t"
        "@P bra.uni DONE_%=;\n\t"
        "bra.uni WAIT_%=;\n\t"
        "DONE_%=:\n\t"
        "}"
        :: "r"(addr), "r"(parity) : "memory");
}

__global__ void __launch_bounds__(BLK) spike_loss_kernel(
    const float* __restrict__ outputs,
    const float* __restrict__ target,
    const int* __restrict__ n_steps_p,
    const int* __restrict__ tau_p,
    long long total_elems,
    float* __restrict__ out)
{
    extern __shared__ float smem[];
    __shared__ alignas(8) unsigned long long mbar_store[NWARP][NSLOT];

    const int   T       = *n_steps_p;
    const float inv_tau = 1.0f / (float)(*tau_p);
    const float decay   = 1.0f - inv_tau;
    const long long rows = (T > 0) ? total_elems / (long long)T : 0;

    const int tid  = threadIdx.x;
    const int wid  = tid >> 5;
    const int lane = tid & 31;
    float acc = 0.0f;

    const bool fast = (T >= 4) && ((T & 3) == 0) && (WROWS * T * 4 <= SLOT_BYTES);

    long long fast_rows = 0;

    if (fast) {
        // ===== fast path: per-warp bulk-copy pipeline, CONTIGUOUS group ranges =====
        const unsigned sm_base   = (unsigned)__cvta_generic_to_shared(smem);
        const unsigned mbar_base = (unsigned)__cvta_generic_to_shared(&mbar_store[0][0]);

        if (tid == 0) {
            #pragma unroll
            for (int i = 0; i < NWARP * NSLOT; ++i)
                mbar_init(mbar_base + 8u * i, 1);
        }
        __syncthreads();

        const long long ngroups = rows / WROWS;
        fast_rows = ngroups * WROWS;
        const int nstreams = GRID * NWARP;             // 608 independent streams
        const int sid      = blockIdx.x * NWARP + wid;

        // balanced contiguous range [g_start, g_start + n_ci)
        const long long base = ngroups / nstreams;
        const long long rem  = ngroups % nstreams;
        const long long g_start = (long long)sid * base + ((long long)sid < rem ? sid : rem);
        const long long n_ci    = base + ((long long)sid < rem ? 1 : 0);

        const unsigned bytes_arr = (unsigned)(WROWS * T * 4);
        const int T4 = T >> 2;

        auto slot_f = [&](int s, int a) -> unsigned {
            return (unsigned)(((wid * NSLOT + s) * 2 + a) * SLOT_FLOATS);
        };
        auto mb_addr = [&](int s) -> unsigned {
            return mbar_base + 8u * (unsigned)(wid * NSLOT + s);
        };

        auto issue = [&](long long ci) {
            const int s = (int)(ci & 1);
            const long long e0 = (g_start + ci) * (long long)WROWS * T;  // sequential walk
            if (lane == 0) {
                const unsigned mb = mb_addr(s);
                mbar_expect_tx(mb, 2 * bytes_arr);
                bulk_g2s(sm_base + slot_f(s, 0) * 4, target  + e0, bytes_arr, mb);
                bulk_g2s(sm_base + slot_f(s, 1) * 4, outputs + e0, bytes_arr, mb);
            }
        };

        if (n_ci > 0) issue(0);
        if (n_ci > 1) issue(1);

        for (long long ci = 0; ci < n_ci; ++ci) {
            const int s = (int)(ci & 1);
            mbar_wait(mb_addr(s), (unsigned)((ci >> 1) & 1));

            // lane = row within group; stride T floats (conflict-free for T%8==4)
            const float4* xt = (const float4*)(smem + slot_f(s, 0) + lane * T);
            const float4* xo = (const float4*)(smem + slot_f(s, 1) + lane * T);
            float syn = 0.0f;
            #pragma unroll 5
            for (int j = 0; j < T4; ++j) {
                const float4 x = xt[j];
                const float4 o = xo[j];
                float e;
                syn = fmaf(syn, decay, x.x); e = fmaf(-syn, inv_tau, o.x); acc = fmaf(e, e, acc);
                syn = fmaf(syn, decay, x.y); e = fmaf(-syn, inv_tau, o.y); acc = fmaf(e, e, acc);
                syn = fmaf(syn, decay, x.z); e = fmaf(-syn, inv_tau, o.z); acc = fmaf(e, e, acc);
                syn = fmaf(syn, decay, x.w); e = fmaf(-syn, inv_tau, o.w); acc = fmaf(e, e, acc);
            }

            __syncwarp();                       // all lanes done reading slot s
            if (ci + 2 < n_ci) issue(ci + 2);   // refill the slot just vacated
        }
    }

    // ===== tail / generic path: scalar thread-per-row from global =====
    if (T > 0) {
        for (long long row = fast_rows + (long long)blockIdx.x * BLK + tid;
             row < rows; row += (long long)GRID * BLK) {
            const float* tg = target  + row * (long long)T;
            const float* op = outputs + row * (long long)T;
            float syn = 0.0f;
            for (int t = 0; t < T; ++t) {
                syn = fmaf(syn, decay, tg[t]);
                const float e = fmaf(-syn, inv_tau, op[t]);
                acc = fmaf(e, e, acc);
            }
        }
    }

    // ---- block reduce ----
    #pragma unroll
    for (int off = 16; off > 0; off >>= 1)
        acc += __shfl_xor_sync(0xFFFFFFFF, acc, off);

    __shared__ float wsum[NWARP];
    if (lane == 0) wsum[wid] = acc;
    __syncthreads();

    __shared__ bool is_last;
    if (tid == 0) {
        float s = 0.0f;
        #pragma unroll
        for (int i = 0; i < NWARP; ++i) s += wsum[i];
        g_partials[blockIdx.x] = s;
        __threadfence();
        const unsigned prev = atomicInc(&g_tick, GRID - 1);   // wraps to 0 each launch
        is_last = (prev == GRID - 1);
    }
    __syncthreads();

    if (is_last) {
        double d = 0.0;
        for (int i = tid; i < GRID; i += BLK)
            d += (double)g_partials[i];
        #pragma unroll
        for (int off = 16; off > 0; off >>= 1)
            d += __shfl_xor_sync(0xFFFFFFFF, d, off);
        __shared__ double dsum[NWARP];
        if (lane == 0) dsum[wid] = d;
        __syncthreads();
        if (tid == 0) {
            double t = 0.0;
            #pragma unroll
            for (int i = 0; i < NWARP; ++i) t += dsum[i];
            out[0] = (float)(0.5 * t);
        }
    }
}

extern "C" void kernel_launch(void* const* d_in, const int* in_sizes, int n_in,
                              void* d_out, int out_size)
{
    const float* outputs = (const float*)d_in[0];
    const float* target  = (const float*)d_in[1];
    const int*   n_steps = (const int*)d_in[2];
    const int*   tau_s   = (const int*)d_in[3];
    float*       out     = (float*)d_out;

    const long long total = (long long)in_sizes[0];

    cudaFuncSetAttribute(spike_loss_kernel,
                         cudaFuncAttributeMaxDynamicSharedMemorySize, SMEM_BYTES);
    spike_loss_kernel<<<GRID, BLK, SMEM_BYTES>>>(outputs, target, n_steps, tau_s, total, out);
}